// round 3
// baseline (speedup 1.0000x reference)
#include <cuda_runtime.h>
#include <cuda_bf16.h>
#include <cstdint>
#include <cstddef>

// Problem constants
#define BB   512
#define TT   128
#define DIN  128
#define DHID 256

// ---------------------------------------------------------------------------
// Scratch (device globals; no allocations allowed)
// ---------------------------------------------------------------------------
__device__ float g_xg [(size_t)BB * TT * 4 * DHID];  // 256 MB : xg buffer (reused per layer)
__device__ float g_seq[(size_t)BB * TT * DHID];      //  64 MB : e0 / d0 / d1 (reused)
__device__ float g_hT [(size_t)BB * DHID];           // final hidden of enc1
__device__ float g_xgd0[(size_t)BB * 4 * DIN];       // dec0 xg (constant over t)

// ---------------------------------------------------------------------------
// Helpers
// ---------------------------------------------------------------------------
__device__ __forceinline__ float sigf(float x) { return 1.0f / (1.0f + __expf(-x)); }

__device__ __forceinline__ uint32_t smem_u32(const void* p) {
    uint32_t a;
    asm("{ .reg .u64 t; cvta.to.shared.u64 t, %1; cvt.u32.u64 %0, t; }" : "=r"(a) : "l"(p));
    return a;
}
__device__ __forceinline__ uint32_t cl_rank() {
    uint32_t r; asm("mov.u32 %0, %%cluster_ctarank;" : "=r"(r)); return r;
}
__device__ __forceinline__ uint32_t mapa_u32(uint32_t addr, uint32_t rank) {
    uint32_t r;
    asm("mapa.shared::cluster.u32 %0, %1, %2;" : "=r"(r) : "r"(addr), "r"(rank));
    return r;
}
__device__ __forceinline__ void st_cluster_v4(uint32_t addr, float a, float b, float c, float d) {
    asm volatile("st.shared::cluster.v4.f32 [%0], {%1,%2,%3,%4};"
                 :: "r"(addr), "f"(a), "f"(b), "f"(c), "f"(d) : "memory");
}
#define CLUSTER_SYNC_() do { \
    asm volatile("barrier.cluster.arrive.aligned;" ::: "memory"); \
    asm volatile("barrier.cluster.wait.aligned;"   ::: "memory"); \
} while (0)

// ---------------------------------------------------------------------------
// Recurrent LSTM kernel.
//   Cluster of 8 CTAs per batch-tile of 32. CTA rank r owns hidden columns
//   [r*JC, r*JC+JC). Whh slice (rows {g*H + r*JC + cl}) lives in SMEM,
//   transposed to k-major. h (full H) is replicated per CTA, double-buffered;
//   each step every CTA broadcasts its new h-slice to all 8 peers via DSMEM,
//   then one cluster barrier.
//   xg layout: xg[(b0+b)*xg_b_stride + t*xg_t_stride + g*H + k]
// ---------------------------------------------------------------------------
template <int H>
__global__ void __cluster_dims__(8, 1, 1) __launch_bounds__(256, 1)
lstm_rec_kernel(const float* __restrict__ Whh,        // [4H][H]
                const float* __restrict__ xg,
                size_t xg_b_stride, int xg_t_stride,
                float* __restrict__ out_seq,           // [B][T][H] or null
                float* __restrict__ out_final)         // [B][H]    or null
{
    constexpr int K   = H;        // dot length
    constexpr int JC  = H / 8;    // hidden columns per CTA
    constexpr int GR  = 4 * JC;   // gate rows per CTA
    constexpr int JT  = GR / 32;  // j's per thread (4 for H=256, 2 for H=128)
    constexpr int HSS = 36;       // padded batch stride inside h_s rows
    constexpr int Bt  = 32;

    extern __shared__ float smem[];
    float* w_s = smem;                       // [K][GR]   k-major
    float* h_s = w_s + K * GR;               // [2][K][HSS]
    float* gsm = h_s + 2 * K * HSS;          // [GR][HSS] raw dots
    float* c_s = gsm + GR * HSS;             // [Bt][JC]

    const int tid = threadIdx.x;
    const uint32_t r = cl_rank();
    const int cid = blockIdx.x >> 3;
    const int b0  = cid * Bt;

    // ---- load Whh slice, transposed to w_s[k][j] -------------------------
    for (int idx = tid; idx < GR * K; idx += 256) {
        int j = idx / K, k = idx % K;             // consecutive tid -> consecutive k
        int g = j / JC, cl = j % JC;
        w_s[k * GR + j] = Whh[(size_t)(g * H + r * JC + cl) * K + k];
    }
    // ---- zero state ------------------------------------------------------
    for (int idx = tid; idx < 2 * K * HSS; idx += 256) h_s[idx] = 0.0f;
    for (int idx = tid; idx < Bt * JC;     idx += 256) c_s[idx] = 0.0f;
    __syncthreads();
    CLUSTER_SYNC_();

    const uint32_t sbase = smem_u32(smem);
    const uint32_t hs_byte = (uint32_t)(K * GR) * 4u;   // byte offset of h_s

    const int bg = tid >> 5;        // 0..7  -> batch quad (b = bg*4 .. +3)
    const int jg = tid & 31;        // 0..31 -> j group (j = jg*JT .. +JT-1)

    for (int t = 0; t < TT; ++t) {
        // ================= phase 1: dots ==================================
        const float* hb = h_s + (size_t)(t & 1) * (K * HSS);
        float acc[4][JT];
        #pragma unroll
        for (int bi = 0; bi < 4; ++bi)
            #pragma unroll
            for (int ji = 0; ji < JT; ++ji) acc[bi][ji] = 0.0f;

        #pragma unroll 4
        for (int k = 0; k < K; ++k) {
            float4 hv = *reinterpret_cast<const float4*>(hb + k * HSS + (bg << 2));
            float wv[JT];
            if constexpr (JT == 4) {
                float4 w4 = *reinterpret_cast<const float4*>(w_s + k * GR + (jg << 2));
                wv[0] = w4.x; wv[1] = w4.y; wv[2] = w4.z; wv[3] = w4.w;
            } else {
                float2 w2 = *reinterpret_cast<const float2*>(w_s + k * GR + (jg << 1));
                wv[0] = w2.x; wv[1] = w2.y;
            }
            float hvv[4] = {hv.x, hv.y, hv.z, hv.w};
            #pragma unroll
            for (int bi = 0; bi < 4; ++bi)
                #pragma unroll
                for (int ji = 0; ji < JT; ++ji)
                    acc[bi][ji] += hvv[bi] * wv[ji];
        }
        #pragma unroll
        for (int ji = 0; ji < JT; ++ji) {
            float4 v = make_float4(acc[0][ji], acc[1][ji], acc[2][ji], acc[3][ji]);
            *reinterpret_cast<float4*>(gsm + (jg * JT + ji) * HSS + (bg << 2)) = v;
        }
        __syncthreads();

        // ================= phase 2: gates + state + broadcast =============
        const float* xgt = xg + (size_t)t * xg_t_stride;
        const int items = 8 * JC;                 // quads of batch
        for (int it = tid; it < items; it += 256) {
            int cl = it % JC;
            int bq = it / JC;
            int bb = bq << 2;
            int kk = r * JC + cl;

            float hq[4];
            #pragma unroll
            for (int q = 0; q < 4; ++q) {
                int b = bb + q;
                size_t bo = (size_t)(b0 + b) * xg_b_stride + kk;
                float gi = gsm[(0 * JC + cl) * HSS + b] + xgt[bo + 0 * H];
                float gf = gsm[(1 * JC + cl) * HSS + b] + xgt[bo + 1 * H];
                float gg = gsm[(2 * JC + cl) * HSS + b] + xgt[bo + 2 * H];
                float go = gsm[(3 * JC + cl) * HSS + b] + xgt[bo + 3 * H];
                float i_ = sigf(gi), f_ = sigf(gf), o_ = sigf(go);
                float g_ = tanhf(gg);
                float c  = f_ * c_s[b * JC + cl] + i_ * g_;
                c_s[b * JC + cl] = c;
                float h  = o_ * tanhf(c);
                hq[q] = h;
                if (out_seq)
                    out_seq[((size_t)(b0 + b) * TT + t) * H + kk] = h;
            }
            // broadcast h quad to all 8 peers' next h buffer
            uint32_t loff = sbase + hs_byte +
                (uint32_t)(((((t + 1) & 1) * K + kk) * HSS + bb) * 4);
            #pragma unroll
            for (int p = 0; p < 8; ++p) {
                uint32_t ra = mapa_u32(loff, (uint32_t)p);
                st_cluster_v4(ra, hq[0], hq[1], hq[2], hq[3]);
            }
        }
        __syncthreads();
        CLUSTER_SYNC_();
    }

    if (out_final) {
        const float* hf = h_s + (size_t)(TT & 1) * (K * HSS);
        for (int idx = tid; idx < Bt * JC; idx += 256) {
            int cl = idx % JC, b = idx / JC;
            out_final[(size_t)(b0 + b) * H + r * JC + cl] = hf[(r * JC + cl) * HSS + b];
        }
    }
}

// ---------------------------------------------------------------------------
// SGEMM with fused bias: C[m][n] = sum_k A[m][k]*B[n][k] + b1[n] (+ b2[n])
// BM=128 BN=64 BK=16, 256 threads, 8x4 micro-tile.
// ---------------------------------------------------------------------------
__global__ __launch_bounds__(256) void sgemm_bias_kernel(
    const float* __restrict__ A, const float* __restrict__ B,
    const float* __restrict__ b1, const float* __restrict__ b2,
    float* __restrict__ C, int M, int N, int K)
{
    __shared__ float As[16][132];
    __shared__ float Bs[16][68];

    const int tid = threadIdx.x;
    const int bm = blockIdx.y * 128;
    const int bn = blockIdx.x * 64;
    const int tx = tid & 15;         // n group
    const int ty = tid >> 4;         // m group
    const int lrow = tid >> 2;       // 0..63
    const int lcol = (tid & 3) << 2; // 0,4,8,12

    float acc[8][4];
    #pragma unroll
    for (int i = 0; i < 8; ++i)
        #pragma unroll
        for (int j = 0; j < 4; ++j) acc[i][j] = 0.0f;

    const float* Ap0 = A + (size_t)(bm + lrow) * K + lcol;
    const float* Ap1 = A + (size_t)(bm + lrow + 64) * K + lcol;
    const float* Bp  = B + (size_t)(bn + lrow) * K + lcol;

    for (int k0 = 0; k0 < K; k0 += 16) {
        float4 a0 = *reinterpret_cast<const float4*>(Ap0 + k0);
        float4 a1 = *reinterpret_cast<const float4*>(Ap1 + k0);
        float4 bv = *reinterpret_cast<const float4*>(Bp + k0);
        As[lcol + 0][lrow]      = a0.x; As[lcol + 1][lrow]      = a0.y;
        As[lcol + 2][lrow]      = a0.z; As[lcol + 3][lrow]      = a0.w;
        As[lcol + 0][lrow + 64] = a1.x; As[lcol + 1][lrow + 64] = a1.y;
        As[lcol + 2][lrow + 64] = a1.z; As[lcol + 3][lrow + 64] = a1.w;
        Bs[lcol + 0][lrow] = bv.x; Bs[lcol + 1][lrow] = bv.y;
        Bs[lcol + 2][lrow] = bv.z; Bs[lcol + 3][lrow] = bv.w;
        __syncthreads();

        #pragma unroll
        for (int k = 0; k < 16; ++k) {
            float av[8], bw[4];
            *reinterpret_cast<float4*>(av)     = *reinterpret_cast<const float4*>(&As[k][ty * 8]);
            *reinterpret_cast<float4*>(av + 4) = *reinterpret_cast<const float4*>(&As[k][ty * 8 + 4]);
            *reinterpret_cast<float4*>(bw)     = *reinterpret_cast<const float4*>(&Bs[k][tx * 4]);
            #pragma unroll
            for (int i = 0; i < 8; ++i)
                #pragma unroll
                for (int j = 0; j < 4; ++j)
                    acc[i][j] += av[i] * bw[j];
        }
        __syncthreads();
    }

    float bias[4];
    #pragma unroll
    for (int j = 0; j < 4; ++j) {
        int n = bn + tx * 4 + j;
        bias[j] = b1[n] + (b2 ? b2[n] : 0.0f);
    }
    #pragma unroll
    for (int i = 0; i < 8; ++i) {
        float4 o = make_float4(acc[i][0] + bias[0], acc[i][1] + bias[1],
                               acc[i][2] + bias[2], acc[i][3] + bias[3]);
        *reinterpret_cast<float4*>(C + (size_t)(bm + ty * 8 + i) * N + bn + tx * 4) = o;
    }
}

// ---------------------------------------------------------------------------
// Launch
// ---------------------------------------------------------------------------
static const int SMEM_REC256 = (DHID * DHID / 2 + 94 * DHID) * 4;  // 227328 B
static const int SMEM_REC128 = (DIN  * DIN  / 2 + 94 * DIN ) * 4;  //  80896 B

extern "C" void kernel_launch(void* const* d_in, const int* in_sizes, int n_in,
                              void* d_out, int out_size)
{
    (void)in_sizes; (void)n_in; (void)out_size;
    const float* x        = (const float*)d_in[0];
    const float* e0_Wih   = (const float*)d_in[1];
    const float* e0_Whh   = (const float*)d_in[2];
    const float* e0_bih   = (const float*)d_in[3];
    const float* e0_bhh   = (const float*)d_in[4];
    const float* e1_Wih   = (const float*)d_in[5];
    const float* e1_Whh   = (const float*)d_in[6];
    const float* e1_bih   = (const float*)d_in[7];
    const float* e1_bhh   = (const float*)d_in[8];
    const float* d0_Wih   = (const float*)d_in[9];
    const float* d0_Whh   = (const float*)d_in[10];
    const float* d0_bih   = (const float*)d_in[11];
    const float* d0_bhh   = (const float*)d_in[12];
    const float* d1_Wih   = (const float*)d_in[13];
    const float* d1_Whh   = (const float*)d_in[14];
    const float* d1_bih   = (const float*)d_in[15];
    const float* d1_bhh   = (const float*)d_in[16];
    const float* out_W    = (const float*)d_in[17];
    const float* out_b    = (const float*)d_in[18];
    float* out = (float*)d_out;

    float *xg, *seq, *hT, *xgd0;
    cudaGetSymbolAddress((void**)&xg,   g_xg);
    cudaGetSymbolAddress((void**)&seq,  g_seq);
    cudaGetSymbolAddress((void**)&hT,   g_hT);
    cudaGetSymbolAddress((void**)&xgd0, g_xgd0);

    cudaFuncSetAttribute(lstm_rec_kernel<DHID>,
                         cudaFuncAttributeMaxDynamicSharedMemorySize, SMEM_REC256);
    cudaFuncSetAttribute(lstm_rec_kernel<DIN>,
                         cudaFuncAttributeMaxDynamicSharedMemorySize, SMEM_REC128);

    const int MT = BB * TT;  // 65536

    // 1) xg0 = x @ enc0_Wih^T + b   [65536, 1024]
    sgemm_bias_kernel<<<dim3(4 * DHID / 64, MT / 128), 256>>>(
        x, e0_Wih, e0_bih, e0_bhh, xg, MT, 4 * DHID, DIN);

    // 2) enc0 recurrence -> e0 (seq)
    lstm_rec_kernel<DHID><<<128, 256, SMEM_REC256>>>(
        e0_Whh, xg, (size_t)TT * 4 * DHID, 4 * DHID, seq, nullptr);

    // 3) xg1 = e0 @ enc1_Wih^T + b   [65536, 1024]
    sgemm_bias_kernel<<<dim3(4 * DHID / 64, MT / 128), 256>>>(
        seq, e1_Wih, e1_bih, e1_bhh, xg, MT, 4 * DHID, DHID);

    // 4) enc1 recurrence -> hT only
    lstm_rec_kernel<DHID><<<128, 256, SMEM_REC256>>>(
        e1_Whh, xg, (size_t)TT * 4 * DHID, 4 * DHID, nullptr, hT);

    // 5) dec0 xg (constant over t): hT @ dec0_Wih^T + b   [512, 512]
    sgemm_bias_kernel<<<dim3(4 * DIN / 64, BB / 128), 256>>>(
        hT, d0_Wih, d0_bih, d0_bhh, xgd0, BB, 4 * DIN, DHID);

    // 6) dec0 recurrence (t-stride 0) -> d0 (seq)
    lstm_rec_kernel<DIN><<<128, 256, SMEM_REC128>>>(
        d0_Whh, xgd0, (size_t)4 * DIN, 0, seq, nullptr);

    // 7) xgd1 = d0 @ dec1_Wih^T + b   [65536, 512]
    sgemm_bias_kernel<<<dim3(4 * DIN / 64, MT / 128), 256>>>(
        seq, d1_Wih, d1_bih, d1_bhh, xg, MT, 4 * DIN, DIN);

    // 8) dec1 recurrence -> d1 (seq, overwrites d0; only xg is read)
    lstm_rec_kernel<DIN><<<128, 256, SMEM_REC128>>>(
        d1_Whh, xg, (size_t)TT * 4 * DIN, 4 * DIN, seq, nullptr);

    // 9) out = d1 @ out_W^T + out_b   [65536, 128]
    sgemm_bias_kernel<<<dim3(DIN / 64, MT / 128), 256>>>(
        seq, out_W, out_b, nullptr, out, MT, DIN, DIN);
}